// round 5
// baseline (speedup 1.0000x reference)
#include <cuda_runtime.h>
#include <cuda_bf16.h>
#include <math.h>
#include <cstdint>

#define NN   50000
#define EE   300000
#define IN_F 128
#define HH   256      // H = HF*AH
#define RR   3
#define AHD  4
#define HF   64
#define RH   (RR*HH)  // 768
#define NR   (NN*RR)  // 150000 segments

// ---------------- scratch (device globals; no allocation allowed) ----------
__device__ float g_hw[(size_t)RR*NN*HH];   // per-relation slabs [r][N][256]
__device__ float g_oacc[(size_t)RR*NN*HH]; // per-relation slabs [r][N][256]
__device__ float g_as[NN];
__device__ float g_ad[NN];
__device__ float g_p[NN*RR*AHD];
__device__ float g_q[NN*RR*AHD];
__device__ float g_ex[(size_t)RR*EE*AHD]; // exp(alpha) (unsigned)
__device__ float g_sgn[RR*EE];            // per-edge sign
__device__ float g_wall[28*IN_F];         // 24 folded p/q dirs + us + ud (+2 pad rows)
__device__ float g_wallc[28];             // constants per projection
__device__ float g_wWt[RR*HH*IN_F];       // wW transposed -> [r][n=256][k=128]
__device__ float g_linWt[HH*RH];          // linW transposed -> [n=256][k=768]
// CSR scratch
__device__ int   g_cnt[NR];
__device__ int   g_off[NR+1];
__device__ int   g_pos[NR];
__device__ int   g_elist[RR*EE];

// ---------------- helpers --------------------------------------------------
__device__ __forceinline__ float lrelu(float x) { return x > 0.f ? x : 0.01f * x; }

// ================= bf16 split mma.sync GEMM ================================
__device__ __forceinline__ void mma16816(float* c, const uint32_t* a, uint32_t b0, uint32_t b1) {
    asm volatile(
        "mma.sync.aligned.m16n8k16.row.col.f32.bf16.bf16.f32 "
        "{%0,%1,%2,%3}, {%4,%5,%6,%7}, {%8,%9}, {%0,%1,%2,%3};"
        : "+f"(c[0]), "+f"(c[1]), "+f"(c[2]), "+f"(c[3])
        : "r"(a[0]), "r"(a[1]), "r"(a[2]), "r"(a[3]), "r"(b0), "r"(b1));
}

__device__ __forceinline__ void cvt_store(char* hi_base, char* lo_base, int soff, float4 v) {
    __nv_bfloat162 h01 = __floats2bfloat162_rn(v.x, v.y);
    __nv_bfloat162 h23 = __floats2bfloat162_rn(v.z, v.w);
    float lx = v.x - __low2float(h01),  ly = v.y - __high2float(h01);
    float lz = v.z - __low2float(h23),  lw = v.w - __high2float(h23);
    __nv_bfloat162 l01 = __floats2bfloat162_rn(lx, ly);
    __nv_bfloat162 l23 = __floats2bfloat162_rn(lz, lw);
    uint2 hu, lu;
    hu.x = *(uint32_t*)&h01; hu.y = *(uint32_t*)&h23;
    lu.x = *(uint32_t*)&l01; lu.y = *(uint32_t*)&l23;
    *(uint2*)(hi_base + soff) = hu;
    *(uint2*)(lo_base + soff) = lu;
}

// A fetch is K-segmented: element (row, k) at A[(k>>a_shift)*a_segstride + row*lda + (k & mask)].
// For unsegmented A pass a_shift=30.
__global__ void __launch_bounds__(256) mma_gemm_kernel(
    const float* __restrict__ A, int lda, int a_shift, size_t a_segstride,
    const float* __restrict__ Bt, int ldb,
    const float* __restrict__ bias,
    float* __restrict__ C, int ldc,
    int M, int K)
{
    __shared__ __align__(16) char sAh[8192];
    __shared__ __align__(16) char sAl[8192];
    __shared__ __align__(16) char sBh[8192];
    __shared__ __align__(16) char sBl[8192];

    int tid = threadIdx.x;
    int wid = tid >> 5, lane = tid & 31;
    int g = lane >> 2, tig = lane & 3;
    int wm = wid & 3, wn = wid >> 2;
    int bm = blockIdx.y * 128, bn = blockIdx.x * 128;
    int amask = (1 << a_shift) - 1;

    float c[2][8][4];
    #pragma unroll
    for (int t = 0; t < 2; t++)
        #pragma unroll
        for (int nt = 0; nt < 8; nt++)
            #pragma unroll
            for (int i = 0; i < 4; i++) c[t][nt][i] = 0.f;

    int nch = K >> 5;
    float4 areg[4], breg[4];
    int rrow[4], rkq[4];

    #pragma unroll
    for (int i = 0; i < 4; i++) {
        int lin = i * 256 + tid;
        int row = lin >> 3, kq = (lin & 7) << 2;
        rrow[i] = row; rkq[i] = kq;
        int gr = bm + row;
        int seg = kq >> a_shift, kin = kq & amask;
        areg[i] = (gr < M) ? *(const float4*)(A + (size_t)seg * a_segstride + (size_t)gr * lda + kin)
                           : make_float4(0.f, 0.f, 0.f, 0.f);
        breg[i] = *(const float4*)(Bt + (size_t)(bn + row) * ldb + kq);
    }
    #pragma unroll
    for (int i = 0; i < 4; i++) {
        int soff = rrow[i] * 64 + ((rkq[i] << 1) ^ ((rrow[i] & 7) << 3));
        cvt_store(sAh, sAl, soff, areg[i]);
        cvt_store(sBh, sBl, soff, breg[i]);
    }
    __syncthreads();

    for (int ch = 0; ch < nch; ch++) {
        bool more = (ch + 1) < nch;
        if (more) {
            int kc = (ch + 1) << 5;
            #pragma unroll
            for (int i = 0; i < 4; i++) {
                int gr = bm + rrow[i];
                int kk = kc + rkq[i];
                int seg = kk >> a_shift, kin = kk & amask;
                areg[i] = (gr < M) ? *(const float4*)(A + (size_t)seg * a_segstride + (size_t)gr * lda + kin)
                                   : make_float4(0.f, 0.f, 0.f, 0.f);
                breg[i] = *(const float4*)(Bt + (size_t)(bn + rrow[i]) * ldb + kk);
            }
        }
        #pragma unroll
        for (int ks = 0; ks < 2; ks++) {
            uint32_t ah[2][4], al[2][4];
            int kb = ks * 32 + tig * 4;
            #pragma unroll
            for (int t = 0; t < 2; t++) {
                int r = wm * 32 + t * 16 + g;
                int x = (r & 7) << 3;
                int o0 = r * 64 + (kb ^ x);
                int o2 = r * 64 + ((kb + 16) ^ x);
                ah[t][0] = *(uint32_t*)(sAh + o0);
                ah[t][1] = *(uint32_t*)(sAh + o0 + 512);
                ah[t][2] = *(uint32_t*)(sAh + o2);
                ah[t][3] = *(uint32_t*)(sAh + o2 + 512);
                al[t][0] = *(uint32_t*)(sAl + o0);
                al[t][1] = *(uint32_t*)(sAl + o0 + 512);
                al[t][2] = *(uint32_t*)(sAl + o2);
                al[t][3] = *(uint32_t*)(sAl + o2 + 512);
            }
            #pragma unroll
            for (int nt = 0; nt < 8; nt++) {
                int n = wn * 64 + nt * 8 + g;
                int x = (n & 7) << 3;
                int o0 = n * 64 + (kb ^ x);
                int o1 = n * 64 + ((kb + 16) ^ x);
                uint32_t bh0 = *(uint32_t*)(sBh + o0);
                uint32_t bh1 = *(uint32_t*)(sBh + o1);
                uint32_t bl0 = *(uint32_t*)(sBl + o0);
                uint32_t bl1 = *(uint32_t*)(sBl + o1);
                #pragma unroll
                for (int t = 0; t < 2; t++) {
                    mma16816(c[t][nt], ah[t], bh0, bh1);
                    mma16816(c[t][nt], ah[t], bl0, bl1);
                    mma16816(c[t][nt], al[t], bh0, bh1);
                }
            }
        }
        if (more) {
            __syncthreads();
            #pragma unroll
            for (int i = 0; i < 4; i++) {
                int soff = rrow[i] * 64 + ((rkq[i] << 1) ^ ((rrow[i] & 7) << 3));
                cvt_store(sAh, sAl, soff, areg[i]);
                cvt_store(sBh, sBl, soff, breg[i]);
            }
            __syncthreads();
        }
    }

    #pragma unroll
    for (int t = 0; t < 2; t++) {
        int row0 = bm + wm * 32 + t * 16 + g;
        #pragma unroll
        for (int nt = 0; nt < 8; nt++) {
            int col = bn + wn * 64 + nt * 8 + tig * 2;
            float b0 = bias[col], b1 = bias[col + 1];
            if (row0 < M) {
                float2 o = make_float2(c[t][nt][0] + b0, c[t][nt][1] + b1);
                *(float2*)(C + (size_t)row0 * ldc + col) = o;
            }
            if (row0 + 8 < M) {
                float2 o = make_float2(c[t][nt][2] + b0, c[t][nt][3] + b1);
                *(float2*)(C + (size_t)(row0 + 8) * ldc + col) = o;
            }
        }
    }
}

// ---------------- weight transposes ----------------------------------------
__global__ void transpose_weights_kernel(const float* __restrict__ wW,
                                         const float* __restrict__ linW) {
    int idx = blockIdx.x * blockDim.x + threadIdx.x;
    if (idx < RR * HH * IN_F) {
        int r = idx / (HH * IN_F);
        int rem = idx - r * HH * IN_F;
        int n = rem / IN_F, k = rem - n * IN_F;
        g_wWt[idx] = wW[(size_t)r * IN_F * HH + (size_t)k * HH + n];
    }
    if (idx < HH * RH) {
        int n = idx / RH, k = idx - n * RH;
        g_linWt[idx] = linW[(size_t)k * HH + n];
    }
}

// ---------------- prep: fold d_liner+f_liner -> wall rows 24/25 ------------
__global__ void prep_kernel(const float* __restrict__ dW, const float* __restrict__ db,
                            const float* __restrict__ fW, const float* __restrict__ fb) {
    int k = threadIdx.x;
    if (k < IN_F) {
        float us = 0.f, ud = 0.f;
        for (int j = 0; j < HH; j++) {
            float w  = dW[k*HH + j];
            float f0 = fW[j], f1 = fW[HH + j], f2 = fW[2*HH + j];
            us += w * (f0 + f2);
            ud += w * (f1 - f2);
        }
        g_wall[24*IN_F + k] = us;
        g_wall[25*IN_F + k] = ud;
        g_wall[26*IN_F + k] = 0.f;
        g_wall[27*IN_F + k] = 0.f;
    }
    if (k == 0) {
        float cs = 0.f, cd = 0.f;
        for (int j = 0; j < HH; j++) {
            float b  = db[j];
            float f0 = fW[j], f1 = fW[HH + j], f2 = fW[2*HH + j];
            cs += b * (f0 + f2);
            cd += b * (f1 - f2);
        }
        g_wallc[24] = cs + fb[0];
        g_wallc[25] = cd;
        g_wallc[26] = 0.f; g_wallc[27] = 0.f;
    }
}

// ---------------- fold w_liner+attention into wall rows 0..23 --------------
__global__ void prep_pq_kernel(const float* __restrict__ wW,
                               const float* __restrict__ wb,
                               const float* __restrict__ aW) {
    int idx = blockIdx.x * blockDim.x + threadIdx.x;
    if (idx < 24 * IN_F) {
        int k = idx & (IN_F - 1);
        int v = idx >> 7;
        int r = v >> 3, rem = v & 7, head = rem >> 1, pq = rem & 1;
        const float* wcol = wW + (size_t)r * IN_F * HH + (size_t)k * HH + head * HF;
        const float* av   = aW + r * 2 * HF + pq * HF;
        float s = 0.f;
        #pragma unroll 8
        for (int i = 0; i < HF; i++) s += wcol[i] * av[i];
        g_wall[idx] = s;
    }
    if (idx < 24) {
        int r = idx >> 3, rem = idx & 7, head = rem >> 1, pq = rem & 1;
        const float* bb = wb + r * HH + head * HF;
        const float* av = aW + r * 2 * HF + pq * HF;
        float s = 0.f;
        for (int i = 0; i < HF; i++) s += bb[i] * av[i];
        g_wallc[idx] = s;
    }
}

// ---------------- per-node projections: smem-tiled -------------------------
__global__ void __launch_bounds__(128) node_kernel(const float* __restrict__ h) {
    __shared__ float sh[64][132];
    __shared__ float sw[28][132];
    __shared__ float sc[28];
    int t = threadIdx.x;
    int nb = blockIdx.x * 64;

    #pragma unroll
    for (int i = 0; i < 16; i++) {
        int lin = i * 128 + t;
        int row = lin >> 5, kq = (lin & 31) << 2;
        int gn = nb + row;
        float4 v = make_float4(0.f, 0.f, 0.f, 0.f);
        if (gn < NN) v = *(const float4*)(h + (size_t)gn * IN_F + kq);
        *(float4*)&sh[row][kq] = v;
    }
    #pragma unroll
    for (int i = 0; i < 7; i++) {
        int lin = i * 128 + t;
        if (lin < 28 * 32) {
            int row = lin >> 5, kq = (lin & 31) << 2;
            *(float4*)&sw[row][kq] = *(const float4*)(g_wall + row * IN_F + kq);
        }
    }
    if (t < 28) sc[t] = g_wallc[t];
    __syncthreads();

    int nrow = t >> 2, sub = t & 3;
    float acc0[7], acc1[7];
    #pragma unroll
    for (int j = 0; j < 7; j++) { acc0[j] = 0.f; acc1[j] = 0.f; }
    for (int k = 0; k < IN_F; k++) {
        float h0 = sh[nrow][k];
        float h1 = sh[nrow + 32][k];
        #pragma unroll
        for (int j = 0; j < 7; j++) {
            float w = sw[sub * 7 + j][k];
            acc0[j] = fmaf(h0, w, acc0[j]);
            acc1[j] = fmaf(h1, w, acc1[j]);
        }
    }
    #pragma unroll
    for (int m = 0; m < 2; m++) {
        int gn = nb + nrow + 32 * m;
        if (gn >= NN) continue;
        #pragma unroll
        for (int j = 0; j < 7; j++) {
            int v = sub * 7 + j;
            if (v >= 26) continue;
            float val = (m ? acc1[j] : acc0[j]) + sc[v];
            if (v < 24) {
                int r = v >> 3, rem = v & 7, head = rem >> 1, pq = rem & 1;
                int off = (gn * RR + r) * AHD + head;
                if (pq == 0) g_p[off] = val; else g_q[off] = val;
            } else if (v == 24) g_as[gn] = val;
            else                g_ad[gn] = val;
        }
    }
}

// ---------------- CSR build ------------------------------------------------
__global__ void count_kernel(const int* __restrict__ dst) {
    int idx = blockIdx.x * blockDim.x + threadIdx.x;
    if (idx >= RR * EE) return;
    int r = idx / EE;
    atomicAdd(&g_cnt[r * NN + dst[idx]], 1);
}

__global__ void __launch_bounds__(1024) scan_kernel() {
    __shared__ int ssum[1024];
    int t = threadIdx.x;
    const int PER = (NR + 1023) / 1024;
    int base = t * PER;
    int s = 0;
    for (int i = 0; i < PER; i++) {
        int idx = base + i;
        if (idx < NR) s += g_cnt[idx];
    }
    ssum[t] = s;
    __syncthreads();
    for (int o = 1; o < 1024; o <<= 1) {
        int w = 0;
        if (t >= o) w = ssum[t - o];
        __syncthreads();
        ssum[t] += w;
        __syncthreads();
    }
    int run = ssum[t] - s;
    for (int i = 0; i < PER; i++) {
        int idx = base + i;
        if (idx < NR) { g_off[idx] = run; run += g_cnt[idx]; }
    }
    if (t == 1023) g_off[NR] = run;
}

__global__ void scatter_kernel(const int* __restrict__ dst) {
    int idx = blockIdx.x * blockDim.x + threadIdx.x;
    if (idx >= RR * EE) return;
    int r = idx / EE;
    int seg = r * NN + dst[idx];
    int p = atomicAdd(&g_pos[seg], 1);
    g_elist[g_off[seg] + p] = idx;
}

// ---------------- edge phase (per relation): sign, alpha, exp --------------
__global__ void edge_kernel(const int* __restrict__ src, const int* __restrict__ dst,
                            const float* __restrict__ ab, int r) {
    int e = blockIdx.x * blockDim.x + threadIdx.x;
    if (e >= EE) return;
    int idx = r * EE + e;
    int s = src[idx], d = dst[idx];
    float sc = g_as[s] + g_ad[d];
    float sg = (sc > 0.f) ? 1.f : ((sc < 0.f) ? -1.f : 0.f);
    float4 pv = *(const float4*)(g_p + (s*RR + r)*AHD);
    float4 qv = *(const float4*)(g_q + (d*RR + r)*AHD);
    float abr = ab[r];
    float4 ex;
    ex.x = expf(lrelu(sg*pv.x + qv.x + abr));
    ex.y = expf(lrelu(sg*pv.y + qv.y + abr));
    ex.z = expf(lrelu(sg*pv.z + qv.z + abr));
    ex.w = expf(lrelu(sg*pv.w + qv.w + abr));
    *(float4*)(g_ex + (size_t)idx * AHD) = ex;
    g_sgn[idx] = sg;
}

// ---------------- CSR aggregate (per relation): warp per dst ---------------
__global__ void aggregate_csr_kernel(const int* __restrict__ src, int r) {
    int gw   = (blockIdx.x * blockDim.x + threadIdx.x) >> 5;
    int lane = threadIdx.x & 31;
    if (gw >= NN) return;
    int seg = r * NN + gw;
    int beg = g_off[seg], end = g_off[seg + 1];
    float* orow = g_oacc + ((size_t)r * NN + gw) * HH + lane * 8;

    if (beg == end) {
        float4 z = make_float4(0.f, 0.f, 0.f, 0.f);
        *(float4*)orow = z;
        *(float4*)(orow + 4) = z;
        return;
    }

    float dx = 0.f, dy = 0.f, dz = 0.f, dw = 0.f;
    for (int j = beg + lane; j < end; j += 32) {
        int idx = g_elist[j];
        float4 e = *(const float4*)(g_ex + (size_t)idx * AHD);
        dx += e.x; dy += e.y; dz += e.z; dw += e.w;
    }
    #pragma unroll
    for (int o = 16; o; o >>= 1) {
        dx += __shfl_xor_sync(0xffffffffu, dx, o);
        dy += __shfl_xor_sync(0xffffffffu, dy, o);
        dz += __shfl_xor_sync(0xffffffffu, dz, o);
        dw += __shfl_xor_sync(0xffffffffu, dw, o);
    }
    int head = lane >> 3;
    float den = (head == 0) ? dx : (head == 1) ? dy : (head == 2) ? dz : dw;
    float deninv = 1.f / den;

    const float* hwbase = g_hw + (size_t)r * NN * HH;
    float a0=0.f,a1=0.f,a2=0.f,a3=0.f,a4=0.f,a5=0.f,a6=0.f,a7=0.f;
    for (int j = beg; j < end; j++) {
        int idx = g_elist[j];
        float ex = g_ex[(size_t)idx * AHD + head];
        float sg = g_sgn[idx];
        int s = src[idx];
        const float4* hr = (const float4*)(hwbase + (size_t)s * HH) + lane * 2;
        float4 v0 = hr[0], v1 = hr[1];
        float cf = ex * deninv * sg;
        a0 = fmaf(cf, v0.x, a0); a1 = fmaf(cf, v0.y, a1);
        a2 = fmaf(cf, v0.z, a2); a3 = fmaf(cf, v0.w, a3);
        a4 = fmaf(cf, v1.x, a4); a5 = fmaf(cf, v1.y, a5);
        a6 = fmaf(cf, v1.z, a6); a7 = fmaf(cf, v1.w, a7);
    }
    *(float4*)orow       = make_float4(a0, a1, a2, a3);
    *(float4*)(orow + 4) = make_float4(a4, a5, a6, a7);
}

// ---------------- launch ---------------------------------------------------
extern "C" void kernel_launch(void* const* d_in, const int* in_sizes, int n_in,
                              void* d_out, int out_size) {
    const float* h    = (const float*)d_in[0];
    const float* dW   = (const float*)d_in[1];
    const float* db   = (const float*)d_in[2];
    const float* fW   = (const float*)d_in[3];
    const float* fb   = (const float*)d_in[4];
    const float* wW   = (const float*)d_in[5];
    const float* wb   = (const float*)d_in[6];
    const float* aW   = (const float*)d_in[7];
    const float* ab   = (const float*)d_in[8];
    const float* linW = (const float*)d_in[9];
    const float* linb = (const float*)d_in[10];
    const int*   src  = (const int*)d_in[11];
    const int*   dst  = (const int*)d_in[12];
    float* out = (float*)d_out;

    float *hw, *oacc, *wWt, *linWt;
    int *cnt, *pos;
    cudaGetSymbolAddress((void**)&hw,    g_hw);
    cudaGetSymbolAddress((void**)&oacc,  g_oacc);
    cudaGetSymbolAddress((void**)&wWt,   g_wWt);
    cudaGetSymbolAddress((void**)&linWt, g_linWt);
    cudaGetSymbolAddress((void**)&cnt,   g_cnt);
    cudaGetSymbolAddress((void**)&pos,   g_pos);

    cudaMemsetAsync(cnt, 0, NR * sizeof(int), 0);
    cudaMemsetAsync(pos, 0, NR * sizeof(int), 0);

    transpose_weights_kernel<<<(HH * RH + 255) / 256, 256>>>(wW, linW);
    prep_kernel<<<1, 128>>>(dW, db, fW, fb);
    prep_pq_kernel<<<(24 * IN_F + 255) / 256, 256>>>(wW, wb, aW);
    node_kernel<<<(NN + 63) / 64, 128>>>(h);

    count_kernel<<<(RR * EE + 255) / 256, 256>>>(dst);
    scan_kernel<<<1, 1024>>>();
    scatter_kernel<<<(RR * EE + 255) / 256, 256>>>(dst);

    int mtiles = (NN + 127) / 128;
    // per-relation pipeline: GEMM -> edge -> aggregate (keeps hw_r hot in L2)
    for (int r = 0; r < RR; r++) {
        mma_gemm_kernel<<<dim3(2, mtiles), 256>>>(
            h, IN_F, 30, 0,
            wWt + (size_t)r * HH * IN_F, IN_F,
            wb + r * HH,
            hw + (size_t)r * NN * HH, HH,
            NN, IN_F);
        edge_kernel<<<(EE + 255) / 256, 256>>>(src, dst, ab, r);
        aggregate_csr_kernel<<<(NN + 7) / 8, 256>>>(src, r);
    }

    // out = concat_r(oacc_r) @ linW + linb  (A segmented by relation slab)
    mma_gemm_kernel<<<dim3(2, mtiles), 256>>>(
        oacc, HH, 8, (size_t)NN * HH,
        linWt, RH,
        linb,
        out, HH,
        NN, RH);
}

// round 9
// speedup vs baseline: 1.0662x; 1.0662x over previous
#include <cuda_runtime.h>
#include <cuda_bf16.h>
#include <cuda_fp16.h>
#include <math.h>
#include <cstdint>

#define NN   50000
#define EE   300000
#define IN_F 128
#define HH   256      // H = HF*AH
#define RR   3
#define AHD  4
#define HF   64
#define RH   (RR*HH)  // 768
#define NR   (NN*RR)  // 150000 segments

// ---------------- scratch (device globals; no allocation allowed) ----------
__device__ __half g_hwh[(size_t)RR*NN*HH];  // h @ wW[r], fp16 slabs [r][N][256] (76.8MB)
__device__ float g_oacc[(size_t)RR*NN*HH];  // aggregated messages, slabs (153.6MB)
__device__ float g_as[NN];
__device__ float g_ad[NN];
__device__ float g_p[NN*RR*AHD];
__device__ float g_q[NN*RR*AHD];
__device__ float g_ex[(size_t)RR*EE*AHD]; // exp(alpha) (unsigned)
__device__ float g_sgn[RR*EE];            // per-edge sign
__device__ float g_wall[28*IN_F];         // 24 folded p/q dirs + us + ud (+2 pad rows)
__device__ float g_wallc[28];             // constants per projection
__device__ float g_wWt[RR*HH*IN_F];       // wW transposed -> [r][n=256][k=128]
__device__ float g_linWt[HH*RH];          // linW transposed -> [n=256][k=768]
// CSR scratch
__device__ int   g_cnt[NR];
__device__ int   g_off[NR+1];
__device__ int   g_pos[NR];
__device__ int   g_elist[RR*EE];

// ---------------- helpers --------------------------------------------------
__device__ __forceinline__ float lrelu(float x) { return x > 0.f ? x : 0.01f * x; }

// ================= bf16 split mma.sync GEMM ================================
__device__ __forceinline__ void mma16816(float* c, const uint32_t* a, uint32_t b0, uint32_t b1) {
    asm volatile(
        "mma.sync.aligned.m16n8k16.row.col.f32.bf16.bf16.f32 "
        "{%0,%1,%2,%3}, {%4,%5,%6,%7}, {%8,%9}, {%0,%1,%2,%3};"
        : "+f"(c[0]), "+f"(c[1]), "+f"(c[2]), "+f"(c[3])
        : "r"(a[0]), "r"(a[1]), "r"(a[2]), "r"(a[3]), "r"(b0), "r"(b1));
}

__device__ __forceinline__ void cvt_store(char* hi_base, char* lo_base, int soff, float4 v) {
    __nv_bfloat162 h01 = __floats2bfloat162_rn(v.x, v.y);
    __nv_bfloat162 h23 = __floats2bfloat162_rn(v.z, v.w);
    float lx = v.x - __low2float(h01),  ly = v.y - __high2float(h01);
    float lz = v.z - __low2float(h23),  lw = v.w - __high2float(h23);
    __nv_bfloat162 l01 = __floats2bfloat162_rn(lx, ly);
    __nv_bfloat162 l23 = __floats2bfloat162_rn(lz, lw);
    uint2 hu, lu;
    hu.x = *(uint32_t*)&h01; hu.y = *(uint32_t*)&h23;
    lu.x = *(uint32_t*)&l01; lu.y = *(uint32_t*)&l23;
    *(uint2*)(hi_base + soff) = hu;
    *(uint2*)(lo_base + soff) = lu;
}

// A fetch is K-segmented: element (row, k) at A[(k>>a_shift)*a_segstride + row*lda + (k&mask)].
// Unsegmented A: a_shift=30. If Ch0 != nullptr, output is written fp16 to Ch0 instead of C0.
__global__ void __launch_bounds__(256) mma_gemm_kernel(
    const float* __restrict__ A, int lda, int a_shift, size_t a_segstride,
    const float* __restrict__ Bt0, int ldb, size_t b_stride,
    const float* __restrict__ bias0, int bias_stride,
    float* __restrict__ C0, __half* __restrict__ Ch0, int ldc, size_t c_stride,
    int M, int K)
{
    __shared__ __align__(16) char sAh[8192];
    __shared__ __align__(16) char sAl[8192];
    __shared__ __align__(16) char sBh[8192];
    __shared__ __align__(16) char sBl[8192];

    const float* Bt   = Bt0   + (size_t)blockIdx.z * b_stride;
    const float* bias = bias0 + (size_t)blockIdx.z * bias_stride;

    int tid = threadIdx.x;
    int wid = tid >> 5, lane = tid & 31;
    int g = lane >> 2, tig = lane & 3;
    int wm = wid & 3, wn = wid >> 2;
    int bm = blockIdx.y * 128, bn = blockIdx.x * 128;
    int amask = (1 << a_shift) - 1;

    float c[2][8][4];
    #pragma unroll
    for (int t = 0; t < 2; t++)
        #pragma unroll
        for (int nt = 0; nt < 8; nt++)
            #pragma unroll
            for (int i = 0; i < 4; i++) c[t][nt][i] = 0.f;

    int nch = K >> 5;
    float4 areg[4], breg[4];
    int rrow[4], rkq[4];

    #pragma unroll
    for (int i = 0; i < 4; i++) {
        int lin = i * 256 + tid;
        int row = lin >> 3, kq = (lin & 7) << 2;
        rrow[i] = row; rkq[i] = kq;
        int gr = bm + row;
        int seg = kq >> a_shift, kin = kq & amask;
        areg[i] = (gr < M) ? *(const float4*)(A + (size_t)seg * a_segstride + (size_t)gr * lda + kin)
                           : make_float4(0.f, 0.f, 0.f, 0.f);
        breg[i] = *(const float4*)(Bt + (size_t)(bn + row) * ldb + kq);
    }
    #pragma unroll
    for (int i = 0; i < 4; i++) {
        int soff = rrow[i] * 64 + ((rkq[i] << 1) ^ ((rrow[i] & 7) << 3));
        cvt_store(sAh, sAl, soff, areg[i]);
        cvt_store(sBh, sBl, soff, breg[i]);
    }
    __syncthreads();

    for (int ch = 0; ch < nch; ch++) {
        bool more = (ch + 1) < nch;
        if (more) {
            int kc = (ch + 1) << 5;
            #pragma unroll
            for (int i = 0; i < 4; i++) {
                int gr = bm + rrow[i];
                int kk = kc + rkq[i];
                int seg = kk >> a_shift, kin = kk & amask;
                areg[i] = (gr < M) ? *(const float4*)(A + (size_t)seg * a_segstride + (size_t)gr * lda + kin)
                                   : make_float4(0.f, 0.f, 0.f, 0.f);
                breg[i] = *(const float4*)(Bt + (size_t)(bn + rrow[i]) * ldb + kk);
            }
        }
        #pragma unroll
        for (int ks = 0; ks < 2; ks++) {
            uint32_t ah[2][4], al[2][4];
            int kb = ks * 32 + tig * 4;
            #pragma unroll
            for (int t = 0; t < 2; t++) {
                int r = wm * 32 + t * 16 + g;
                int x = (r & 7) << 3;
                int o0 = r * 64 + (kb ^ x);
                int o2 = r * 64 + ((kb + 16) ^ x);
                ah[t][0] = *(uint32_t*)(sAh + o0);
                ah[t][1] = *(uint32_t*)(sAh + o0 + 512);
                ah[t][2] = *(uint32_t*)(sAh + o2);
                ah[t][3] = *(uint32_t*)(sAh + o2 + 512);
                al[t][0] = *(uint32_t*)(sAl + o0);
                al[t][1] = *(uint32_t*)(sAl + o0 + 512);
                al[t][2] = *(uint32_t*)(sAl + o2);
                al[t][3] = *(uint32_t*)(sAl + o2 + 512);
            }
            #pragma unroll
            for (int nt = 0; nt < 8; nt++) {
                int n = wn * 64 + nt * 8 + g;
                int x = (n & 7) << 3;
                int o0 = n * 64 + (kb ^ x);
                int o1 = n * 64 + ((kb + 16) ^ x);
                uint32_t bh0 = *(uint32_t*)(sBh + o0);
                uint32_t bh1 = *(uint32_t*)(sBh + o1);
                uint32_t bl0 = *(uint32_t*)(sBl + o0);
                uint32_t bl1 = *(uint32_t*)(sBl + o1);
                #pragma unroll
                for (int t = 0; t < 2; t++) {
                    mma16816(c[t][nt], ah[t], bh0, bh1);
                    mma16816(c[t][nt], ah[t], bl0, bl1);
                    mma16816(c[t][nt], al[t], bh0, bh1);
                }
            }
        }
        if (more) {
            __syncthreads();
            #pragma unroll
            for (int i = 0; i < 4; i++) {
                int soff = rrow[i] * 64 + ((rkq[i] << 1) ^ ((rrow[i] & 7) << 3));
                cvt_store(sAh, sAl, soff, areg[i]);
                cvt_store(sBh, sBl, soff, breg[i]);
            }
            __syncthreads();
        }
    }

    if (Ch0) {
        __half* Ch = Ch0 + (size_t)blockIdx.z * c_stride;
        #pragma unroll
        for (int t = 0; t < 2; t++) {
            int row0 = bm + wm * 32 + t * 16 + g;
            #pragma unroll
            for (int nt = 0; nt < 8; nt++) {
                int col = bn + wn * 64 + nt * 8 + tig * 2;
                float b0 = bias[col], b1 = bias[col + 1];
                if (row0 < M)
                    *(__half2*)(Ch + (size_t)row0 * ldc + col) =
                        __floats2half2_rn(c[t][nt][0] + b0, c[t][nt][1] + b1);
                if (row0 + 8 < M)
                    *(__half2*)(Ch + (size_t)(row0 + 8) * ldc + col) =
                        __floats2half2_rn(c[t][nt][2] + b0, c[t][nt][3] + b1);
            }
        }
    } else {
        float* C = C0 + (size_t)blockIdx.z * c_stride;
        #pragma unroll
        for (int t = 0; t < 2; t++) {
            int row0 = bm + wm * 32 + t * 16 + g;
            #pragma unroll
            for (int nt = 0; nt < 8; nt++) {
                int col = bn + wn * 64 + nt * 8 + tig * 2;
                float b0 = bias[col], b1 = bias[col + 1];
                if (row0 < M) {
                    float2 o = make_float2(c[t][nt][0] + b0, c[t][nt][1] + b1);
                    *(float2*)(C + (size_t)row0 * ldc + col) = o;
                }
                if (row0 + 8 < M) {
                    float2 o = make_float2(c[t][nt][2] + b0, c[t][nt][3] + b1);
                    *(float2*)(C + (size_t)(row0 + 8) * ldc + col) = o;
                }
            }
        }
    }
}

// ---------------- weight transposes ----------------------------------------
__global__ void transpose_weights_kernel(const float* __restrict__ wW,
                                         const float* __restrict__ linW) {
    int idx = blockIdx.x * blockDim.x + threadIdx.x;
    if (idx < RR * HH * IN_F) {
        int r = idx / (HH * IN_F);
        int rem = idx - r * HH * IN_F;
        int n = rem / IN_F, k = rem - n * IN_F;
        g_wWt[idx] = wW[(size_t)r * IN_F * HH + (size_t)k * HH + n];
    }
    if (idx < HH * RH) {
        int n = idx / RH, k = idx - n * RH;
        g_linWt[idx] = linW[(size_t)k * HH + n];
    }
}

// ---------------- prep: fold d_liner+f_liner -> wall rows 24/25 ------------
__global__ void prep_kernel(const float* __restrict__ dW, const float* __restrict__ db,
                            const float* __restrict__ fW, const float* __restrict__ fb) {
    int k = threadIdx.x;
    if (k < IN_F) {
        float us = 0.f, ud = 0.f;
        for (int j = 0; j < HH; j++) {
            float w  = dW[k*HH + j];
            float f0 = fW[j], f1 = fW[HH + j], f2 = fW[2*HH + j];
            us += w * (f0 + f2);
            ud += w * (f1 - f2);
        }
        g_wall[24*IN_F + k] = us;
        g_wall[25*IN_F + k] = ud;
        g_wall[26*IN_F + k] = 0.f;
        g_wall[27*IN_F + k] = 0.f;
    }
    if (k == 0) {
        float cs = 0.f, cd = 0.f;
        for (int j = 0; j < HH; j++) {
            float b  = db[j];
            float f0 = fW[j], f1 = fW[HH + j], f2 = fW[2*HH + j];
            cs += b * (f0 + f2);
            cd += b * (f1 - f2);
        }
        g_wallc[24] = cs + fb[0];
        g_wallc[25] = cd;
        g_wallc[26] = 0.f; g_wallc[27] = 0.f;
    }
}

// ---------------- fold w_liner+attention into wall rows 0..23 --------------
__global__ void prep_pq_kernel(const float* __restrict__ wW,
                               const float* __restrict__ wb,
                               const float* __restrict__ aW) {
    int idx = blockIdx.x * blockDim.x + threadIdx.x;
    if (idx < 24 * IN_F) {
        int k = idx & (IN_F - 1);
        int v = idx >> 7;
        int r = v >> 3, rem = v & 7, head = rem >> 1, pq = rem & 1;
        const float* wcol = wW + (size_t)r * IN_F * HH + (size_t)k * HH + head * HF;
        const float* av   = aW + r * 2 * HF + pq * HF;
        float s = 0.f;
        #pragma unroll 8
        for (int i = 0; i < HF; i++) s += wcol[i] * av[i];
        g_wall[idx] = s;
    }
    if (idx < 24) {
        int r = idx >> 3, rem = idx & 7, head = rem >> 1, pq = rem & 1;
        const float* bb = wb + r * HH + head * HF;
        const float* av = aW + r * 2 * HF + pq * HF;
        float s = 0.f;
        for (int i = 0; i < HF; i++) s += bb[i] * av[i];
        g_wallc[idx] = s;
    }
}

// ---------------- per-node projections: smem-tiled -------------------------
__global__ void __launch_bounds__(128) node_kernel(const float* __restrict__ h) {
    __shared__ float sh[64][132];
    __shared__ float sw[28][132];
    __shared__ float sc[28];
    int t = threadIdx.x;
    int nb = blockIdx.x * 64;

    #pragma unroll
    for (int i = 0; i < 16; i++) {
        int lin = i * 128 + t;
        int row = lin >> 5, kq = (lin & 31) << 2;
        int gn = nb + row;
        float4 v = make_float4(0.f, 0.f, 0.f, 0.f);
        if (gn < NN) v = *(const float4*)(h + (size_t)gn * IN_F + kq);
        *(float4*)&sh[row][kq] = v;
    }
    #pragma unroll
    for (int i = 0; i < 7; i++) {
        int lin = i * 128 + t;
        if (lin < 28 * 32) {
            int row = lin >> 5, kq = (lin & 31) << 2;
            *(float4*)&sw[row][kq] = *(const float4*)(g_wall + row * IN_F + kq);
        }
    }
    if (t < 28) sc[t] = g_wallc[t];
    __syncthreads();

    int nrow = t >> 2, sub = t & 3;
    float acc0[7], acc1[7];
    #pragma unroll
    for (int j = 0; j < 7; j++) { acc0[j] = 0.f; acc1[j] = 0.f; }
    for (int k = 0; k < IN_F; k++) {
        float h0 = sh[nrow][k];
        float h1 = sh[nrow + 32][k];
        #pragma unroll
        for (int j = 0; j < 7; j++) {
            float w = sw[sub * 7 + j][k];
            acc0[j] = fmaf(h0, w, acc0[j]);
            acc1[j] = fmaf(h1, w, acc1[j]);
        }
    }
    #pragma unroll
    for (int m = 0; m < 2; m++) {
        int gn = nb + nrow + 32 * m;
        if (gn >= NN) continue;
        #pragma unroll
        for (int j = 0; j < 7; j++) {
            int v = sub * 7 + j;
            if (v >= 26) continue;
            float val = (m ? acc1[j] : acc0[j]) + sc[v];
            if (v < 24) {
                int r = v >> 3, rem = v & 7, head = rem >> 1, pq = rem & 1;
                int off = (gn * RR + r) * AHD + head;
                if (pq == 0) g_p[off] = val; else g_q[off] = val;
            } else if (v == 24) g_as[gn] = val;
            else                g_ad[gn] = val;
        }
    }
}

// ---------------- CSR build ------------------------------------------------
__global__ void count_kernel(const int* __restrict__ dst) {
    int idx = blockIdx.x * blockDim.x + threadIdx.x;
    if (idx >= RR * EE) return;
    int r = idx / EE;
    atomicAdd(&g_cnt[r * NN + dst[idx]], 1);
}

__global__ void __launch_bounds__(1024) scan_kernel() {
    __shared__ int ssum[1024];
    int t = threadIdx.x;
    const int PER = (NR + 1023) / 1024;
    int base = t * PER;
    int s = 0;
    for (int i = 0; i < PER; i++) {
        int idx = base + i;
        if (idx < NR) s += g_cnt[idx];
    }
    ssum[t] = s;
    __syncthreads();
    for (int o = 1; o < 1024; o <<= 1) {
        int w = 0;
        if (t >= o) w = ssum[t - o];
        __syncthreads();
        ssum[t] += w;
        __syncthreads();
    }
    int run = ssum[t] - s;
    for (int i = 0; i < PER; i++) {
        int idx = base + i;
        if (idx < NR) { g_off[idx] = run; run += g_cnt[idx]; }
    }
    if (t == 1023) g_off[NR] = run;
}

__global__ void scatter_kernel(const int* __restrict__ dst) {
    int idx = blockIdx.x * blockDim.x + threadIdx.x;
    if (idx >= RR * EE) return;
    int r = idx / EE;
    int seg = r * NN + dst[idx];
    int p = atomicAdd(&g_pos[seg], 1);
    g_elist[g_off[seg] + p] = idx;
}

// ---------------- edge phase: sign, alpha, exp (no atomics) ----------------
__global__ void edge_kernel(const int* __restrict__ src, const int* __restrict__ dst,
                            const float* __restrict__ ab) {
    int idx = blockIdx.x * blockDim.x + threadIdx.x;
    if (idx >= RR * EE) return;
    int r = idx / EE;
    int s = src[idx], d = dst[idx];
    float sc = g_as[s] + g_ad[d];
    float sg = (sc > 0.f) ? 1.f : ((sc < 0.f) ? -1.f : 0.f);
    float4 pv = *(const float4*)(g_p + (s*RR + r)*AHD);
    float4 qv = *(const float4*)(g_q + (d*RR + r)*AHD);
    float abr = ab[r];
    float4 ex;
    ex.x = expf(lrelu(sg*pv.x + qv.x + abr));
    ex.y = expf(lrelu(sg*pv.y + qv.y + abr));
    ex.z = expf(lrelu(sg*pv.z + qv.z + abr));
    ex.w = expf(lrelu(sg*pv.w + qv.w + abr));
    *(float4*)(g_ex + (size_t)idx * AHD) = ex;
    g_sgn[idx] = sg;
}

// ---------------- CSR aggregate: warp per (r,dst), fp16 gather -------------
__global__ void __launch_bounds__(256) aggregate_csr_kernel(const int* __restrict__ src) {
    __shared__ float4 scf[8][32];
    __shared__ int    ssrc[8][32];
    int gw   = (blockIdx.x * blockDim.x + threadIdx.x) >> 5;
    int lane = threadIdx.x & 31;
    int wslot = threadIdx.x >> 5;
    if (gw >= NR) return;
    int r = gw / NN;
    int beg = g_off[gw], end = g_off[gw + 1];
    float* orow = g_oacc + (size_t)gw * HH + lane * 8;

    if (beg == end) {
        float4 z = make_float4(0.f, 0.f, 0.f, 0.f);
        *(float4*)orow = z;
        *(float4*)(orow + 4) = z;
        return;
    }

    // denominator over incident edges (4 heads)
    float dx = 0.f, dy = 0.f, dz = 0.f, dw = 0.f;
    for (int j = beg + lane; j < end; j += 32) {
        int idx = g_elist[j];
        float4 e = *(const float4*)(g_ex + (size_t)idx * AHD);
        dx += e.x; dy += e.y; dz += e.z; dw += e.w;
    }
    #pragma unroll
    for (int o = 16; o; o >>= 1) {
        dx += __shfl_xor_sync(0xffffffffu, dx, o);
        dy += __shfl_xor_sync(0xffffffffu, dy, o);
        dz += __shfl_xor_sync(0xffffffffu, dz, o);
        dw += __shfl_xor_sync(0xffffffffu, dw, o);
    }
    float rdx = 1.f / dx, rdy = 1.f / dy, rdz = 1.f / dz, rdw = 1.f / dw;
    int head = lane >> 3;

    const __half* hwbase = g_hwh + (size_t)r * NN * HH;
    float a0=0.f,a1=0.f,a2=0.f,a3=0.f,a4=0.f,a5=0.f,a6=0.f,a7=0.f;

    for (int base = beg; base < end; base += 32) {
        int j = base + lane;
        int cnt = min(32, end - base);
        if (j < end) {
            int idx = g_elist[j];
            float4 e = *(const float4*)(g_ex + (size_t)idx * AHD);
            float sg = g_sgn[idx];
            scf[wslot][lane] = make_float4(sg*e.x*rdx, sg*e.y*rdy, sg*e.z*rdz, sg*e.w*rdw);
            ssrc[wslot][lane] = src[idx];
        }
        __syncwarp();
        #pragma unroll 4
        for (int k = 0; k < cnt; k++) {
            int s = ssrc[wslot][k];
            float4 c4 = scf[wslot][k];
            float cf = (head == 0) ? c4.x : (head == 1) ? c4.y : (head == 2) ? c4.z : c4.w;
            uint4 hv = *(const uint4*)(hwbase + (size_t)s * HH + lane * 8);
            float2 f0 = __half22float2(*(__half2*)&hv.x);
            float2 f1 = __half22float2(*(__half2*)&hv.y);
            float2 f2 = __half22float2(*(__half2*)&hv.z);
            float2 f3 = __half22float2(*(__half2*)&hv.w);
            a0 = fmaf(cf, f0.x, a0); a1 = fmaf(cf, f0.y, a1);
            a2 = fmaf(cf, f1.x, a2); a3 = fmaf(cf, f1.y, a3);
            a4 = fmaf(cf, f2.x, a4); a5 = fmaf(cf, f2.y, a5);
            a6 = fmaf(cf, f3.x, a6); a7 = fmaf(cf, f3.y, a7);
        }
        __syncwarp();
    }
    *(float4*)orow       = make_float4(a0, a1, a2, a3);
    *(float4*)(orow + 4) = make_float4(a4, a5, a6, a7);
}

// ---------------- launch ---------------------------------------------------
extern "C" void kernel_launch(void* const* d_in, const int* in_sizes, int n_in,
                              void* d_out, int out_size) {
    const float* h    = (const float*)d_in[0];
    const float* dW   = (const float*)d_in[1];
    const float* db   = (const float*)d_in[2];
    const float* fW   = (const float*)d_in[3];
    const float* fb   = (const float*)d_in[4];
    const float* wW   = (const float*)d_in[5];
    const float* wb   = (const float*)d_in[6];
    const float* aW   = (const float*)d_in[7];
    const float* ab   = (const float*)d_in[8];
    const float* linW = (const float*)d_in[9];
    const float* linb = (const float*)d_in[10];
    const int*   src  = (const int*)d_in[11];
    const int*   dst  = (const int*)d_in[12];
    float* out = (float*)d_out;

    float *oacc, *wWt, *linWt;
    __half* hwh;
    int *cnt, *pos;
    cudaGetSymbolAddress((void**)&hwh,   g_hwh);
    cudaGetSymbolAddress((void**)&oacc,  g_oacc);
    cudaGetSymbolAddress((void**)&wWt,   g_wWt);
    cudaGetSymbolAddress((void**)&linWt, g_linWt);
    cudaGetSymbolAddress((void**)&cnt,   g_cnt);
    cudaGetSymbolAddress((void**)&pos,   g_pos);

    cudaMemsetAsync(cnt, 0, NR * sizeof(int), 0);
    cudaMemsetAsync(pos, 0, NR * sizeof(int), 0);

    transpose_weights_kernel<<<(HH * RH + 255) / 256, 256>>>(wW, linW);
    prep_kernel<<<1, 128>>>(dW, db, fW, fb);
    prep_pq_kernel<<<(24 * IN_F + 255) / 256, 256>>>(wW, wb, aW);
    node_kernel<<<(NN + 63) / 64, 128>>>(h);

    count_kernel<<<(RR * EE + 255) / 256, 256>>>(dst);
    scan_kernel<<<1, 1024>>>();
    scatter_kernel<<<(RR * EE + 255) / 256, 256>>>(dst);

    int mtiles = (NN + 127) / 128;
    // hw[r] = h @ wW[r] + wb[r] (all relations, fp16 output)
    mma_gemm_kernel<<<dim3(2, mtiles, RR), 256>>>(
        h, IN_F, 30, 0,
        wWt, IN_F, (size_t)HH * IN_F,
        wb, HH,
        nullptr, hwh, HH, (size_t)NN * HH,
        NN, IN_F);

    edge_kernel<<<(RR * EE + 255) / 256, 256>>>(src, dst, ab);
    aggregate_csr_kernel<<<(NR + 7) / 8, 256>>>(src);

    // out = concat_r(oacc_r) @ linW + linb  (A segmented by relation slab)
    mma_gemm_kernel<<<dim3(2, mtiles, 1), 256>>>(
        oacc, HH, 8, (size_t)NN * HH,
        linWt, RH, 0,
        linb, 0,
        out, nullptr, HH, 0,
        NN, RH);
}

// round 13
// speedup vs baseline: 1.4168x; 1.3289x over previous
#include <cuda_runtime.h>
#include <cuda_fp16.h>
#include <math.h>
#include <cstdint>

#define NN   50000
#define EE   300000
#define IN_F 128
#define HH   256      // H = HF*AH
#define RR   3
#define AHD  4
#define HF   64
#define RH   (RR*HH)  // 768
#define NR   (NN*RR)  // 150000 segments

// ---------------- scratch (device globals; no allocation allowed) ----------
__device__ __half g_hwh[(size_t)RR*NN*HH];  // h @ wW[r], fp16 slabs [r][N][256] (76.8MB)
__device__ float g_oacc[(size_t)RR*NN*HH];  // aggregated messages, slabs (153.6MB)
__device__ float g_as[NN];
__device__ float g_ad[NN];
__device__ float g_p[NN*RR*AHD];
__device__ float g_q[NN*RR*AHD];
__device__ float g_ex[(size_t)RR*EE*AHD]; // exp(alpha) (unsigned)
__device__ float g_sgn[RR*EE];            // per-edge sign
__device__ float g_wall[28*IN_F];         // 24 folded p/q dirs + us + ud (+2 pad rows)
__device__ float g_wallc[28];             // constants per projection
__device__ float g_wWt[RR*HH*IN_F];       // wW transposed -> [r][n=256][k=128]
__device__ float g_linWt[HH*RH];          // linW transposed -> [n=256][k=768]
// CSR scratch
__device__ int   g_cnt[NR];
__device__ int   g_off[NR+1];
__device__ int   g_pos[NR];
__device__ int   g_elist[RR*EE];

// ---------------- helpers --------------------------------------------------
__device__ __forceinline__ float lrelu(float x) { return x > 0.f ? x : 0.01f * x; }

// ================= single-pass fp16 mma.sync GEMM ==========================
__device__ __forceinline__ void mma16816h(float* c, const uint32_t* a, uint32_t b0, uint32_t b1) {
    asm volatile(
        "mma.sync.aligned.m16n8k16.row.col.f32.f16.f16.f32 "
        "{%0,%1,%2,%3}, {%4,%5,%6,%7}, {%8,%9}, {%0,%1,%2,%3};"
        : "+f"(c[0]), "+f"(c[1]), "+f"(c[2]), "+f"(c[3])
        : "r"(a[0]), "r"(a[1]), "r"(a[2]), "r"(a[3]), "r"(b0), "r"(b1));
}

__device__ __forceinline__ void cvt_store16(char* base, int soff, float4 v) {
    __half2 h01 = __floats2half2_rn(v.x, v.y);
    __half2 h23 = __floats2half2_rn(v.z, v.w);
    uint2 u;
    u.x = *(uint32_t*)&h01;
    u.y = *(uint32_t*)&h23;
    *(uint2*)(base + soff) = u;
}

// A fetch is K-segmented: element (row, k) at A[(k>>a_shift)*a_segstride + row*lda + (k&mask)].
// Unsegmented A: a_shift=30. If Ch0 != nullptr, output is written fp16 to Ch0 instead of C0.
__global__ void __launch_bounds__(256) mma_gemm_kernel(
    const float* __restrict__ A, int lda, int a_shift, size_t a_segstride,
    const float* __restrict__ Bt0, int ldb, size_t b_stride,
    const float* __restrict__ bias0, int bias_stride,
    float* __restrict__ C0, __half* __restrict__ Ch0, int ldc, size_t c_stride,
    int M, int K)
{
    __shared__ __align__(16) char sA[8192];
    __shared__ __align__(16) char sB[8192];

    const float* Bt   = Bt0   + (size_t)blockIdx.z * b_stride;
    const float* bias = bias0 + (size_t)blockIdx.z * bias_stride;

    int tid = threadIdx.x;
    int wid = tid >> 5, lane = tid & 31;
    int g = lane >> 2, tig = lane & 3;
    int wm = wid & 3, wn = wid >> 2;
    int bm = blockIdx.y * 128, bn = blockIdx.x * 128;
    int amask = (1 << a_shift) - 1;

    float c[2][8][4];
    #pragma unroll
    for (int t = 0; t < 2; t++)
        #pragma unroll
        for (int nt = 0; nt < 8; nt++)
            #pragma unroll
            for (int i = 0; i < 4; i++) c[t][nt][i] = 0.f;

    int nch = K >> 5;
    float4 areg[4], breg[4];
    int rrow[4], rkq[4];

    #pragma unroll
    for (int i = 0; i < 4; i++) {
        int lin = i * 256 + tid;
        int row = lin >> 3, kq = (lin & 7) << 2;
        rrow[i] = row; rkq[i] = kq;
        int gr = bm + row;
        int seg = kq >> a_shift, kin = kq & amask;
        areg[i] = (gr < M) ? *(const float4*)(A + (size_t)seg * a_segstride + (size_t)gr * lda + kin)
                           : make_float4(0.f, 0.f, 0.f, 0.f);
        breg[i] = *(const float4*)(Bt + (size_t)(bn + row) * ldb + kq);
    }
    #pragma unroll
    for (int i = 0; i < 4; i++) {
        int soff = rrow[i] * 64 + ((rkq[i] << 1) ^ ((rrow[i] & 7) << 3));
        cvt_store16(sA, soff, areg[i]);
        cvt_store16(sB, soff, breg[i]);
    }
    __syncthreads();

    for (int ch = 0; ch < nch; ch++) {
        bool more = (ch + 1) < nch;
        if (more) {
            int kc = (ch + 1) << 5;
            #pragma unroll
            for (int i = 0; i < 4; i++) {
                int gr = bm + rrow[i];
                int kk = kc + rkq[i];
                int seg = kk >> a_shift, kin = kk & amask;
                areg[i] = (gr < M) ? *(const float4*)(A + (size_t)seg * a_segstride + (size_t)gr * lda + kin)
                                   : make_float4(0.f, 0.f, 0.f, 0.f);
                breg[i] = *(const float4*)(Bt + (size_t)(bn + rrow[i]) * ldb + kk);
            }
        }
        #pragma unroll
        for (int ks = 0; ks < 2; ks++) {
            uint32_t ah[2][4];
            int kb = ks * 32 + tig * 4;
            #pragma unroll
            for (int t = 0; t < 2; t++) {
                int r = wm * 32 + t * 16 + g;
                int x = (r & 7) << 3;
                int o0 = r * 64 + (kb ^ x);
                int o2 = r * 64 + ((kb + 16) ^ x);
                ah[t][0] = *(uint32_t*)(sA + o0);
                ah[t][1] = *(uint32_t*)(sA + o0 + 512);
                ah[t][2] = *(uint32_t*)(sA + o2);
                ah[t][3] = *(uint32_t*)(sA + o2 + 512);
            }
            #pragma unroll
            for (int nt = 0; nt < 8; nt++) {
                int n = wn * 64 + nt * 8 + g;
                int x = (n & 7) << 3;
                int o0 = n * 64 + (kb ^ x);
                int o1 = n * 64 + ((kb + 16) ^ x);
                uint32_t b0 = *(uint32_t*)(sB + o0);
                uint32_t b1 = *(uint32_t*)(sB + o1);
                #pragma unroll
                for (int t = 0; t < 2; t++)
                    mma16816h(c[t][nt], ah[t], b0, b1);
            }
        }
        if (more) {
            __syncthreads();
            #pragma unroll
            for (int i = 0; i < 4; i++) {
                int soff = rrow[i] * 64 + ((rkq[i] << 1) ^ ((rrow[i] & 7) << 3));
                cvt_store16(sA, soff, areg[i]);
                cvt_store16(sB, soff, breg[i]);
            }
            __syncthreads();
        }
    }

    if (Ch0) {
        __half* Ch = Ch0 + (size_t)blockIdx.z * c_stride;
        #pragma unroll
        for (int t = 0; t < 2; t++) {
            int row0 = bm + wm * 32 + t * 16 + g;
            #pragma unroll
            for (int nt = 0; nt < 8; nt++) {
                int col = bn + wn * 64 + nt * 8 + tig * 2;
                float b0 = bias[col], b1 = bias[col + 1];
                if (row0 < M)
                    *(__half2*)(Ch + (size_t)row0 * ldc + col) =
                        __floats2half2_rn(c[t][nt][0] + b0, c[t][nt][1] + b1);
                if (row0 + 8 < M)
                    *(__half2*)(Ch + (size_t)(row0 + 8) * ldc + col) =
                        __floats2half2_rn(c[t][nt][2] + b0, c[t][nt][3] + b1);
            }
        }
    } else {
        float* C = C0 + (size_t)blockIdx.z * c_stride;
        #pragma unroll
        for (int t = 0; t < 2; t++) {
            int row0 = bm + wm * 32 + t * 16 + g;
            #pragma unroll
            for (int nt = 0; nt < 8; nt++) {
                int col = bn + wn * 64 + nt * 8 + tig * 2;
                float b0 = bias[col], b1 = bias[col + 1];
                if (row0 < M) {
                    float2 o = make_float2(c[t][nt][0] + b0, c[t][nt][1] + b1);
                    *(float2*)(C + (size_t)row0 * ldc + col) = o;
                }
                if (row0 + 8 < M) {
                    float2 o = make_float2(c[t][nt][2] + b0, c[t][nt][3] + b1);
                    *(float2*)(C + (size_t)(row0 + 8) * ldc + col) = o;
                }
            }
        }
    }
}

// ---------------- weight transposes ----------------------------------------
__global__ void transpose_weights_kernel(const float* __restrict__ wW,
                                         const float* __restrict__ linW) {
    int idx = blockIdx.x * blockDim.x + threadIdx.x;
    if (idx < RR * HH * IN_F) {
        int r = idx / (HH * IN_F);
        int rem = idx - r * HH * IN_F;
        int n = rem / IN_F, k = rem - n * IN_F;
        g_wWt[idx] = wW[(size_t)r * IN_F * HH + (size_t)k * HH + n];
    }
    if (idx < HH * RH) {
        int n = idx / RH, k = idx - n * RH;
        g_linWt[idx] = linW[(size_t)k * HH + n];
    }
}

// ---------------- prep: fold d_liner+f_liner -> wall rows 24/25 ------------
__global__ void prep_kernel(const float* __restrict__ dW, const float* __restrict__ db,
                            const float* __restrict__ fW, const float* __restrict__ fb) {
    int k = threadIdx.x;
    if (k < IN_F) {
        float us = 0.f, ud = 0.f;
        for (int j = 0; j < HH; j++) {
            float w  = dW[k*HH + j];
            float f0 = fW[j], f1 = fW[HH + j], f2 = fW[2*HH + j];
            us += w * (f0 + f2);
            ud += w * (f1 - f2);
        }
        g_wall[24*IN_F + k] = us;
        g_wall[25*IN_F + k] = ud;
        g_wall[26*IN_F + k] = 0.f;
        g_wall[27*IN_F + k] = 0.f;
    }
    if (k == 0) {
        float cs = 0.f, cd = 0.f;
        for (int j = 0; j < HH; j++) {
            float b  = db[j];
            float f0 = fW[j], f1 = fW[HH + j], f2 = fW[2*HH + j];
            cs += b * (f0 + f2);
            cd += b * (f1 - f2);
        }
        g_wallc[24] = cs + fb[0];
        g_wallc[25] = cd;
        g_wallc[26] = 0.f; g_wallc[27] = 0.f;
    }
}

// ---------------- fold w_liner+attention into wall rows 0..23 --------------
__global__ void prep_pq_kernel(const float* __restrict__ wW,
                               const float* __restrict__ wb,
                               const float* __restrict__ aW) {
    int idx = blockIdx.x * blockDim.x + threadIdx.x;
    if (idx < 24 * IN_F) {
        int k = idx & (IN_F - 1);
        int v = idx >> 7;
        int r = v >> 3, rem = v & 7, head = rem >> 1, pq = rem & 1;
        const float* wcol = wW + (size_t)r * IN_F * HH + (size_t)k * HH + head * HF;
        const float* av   = aW + r * 2 * HF + pq * HF;
        float s = 0.f;
        #pragma unroll 8
        for (int i = 0; i < HF; i++) s += wcol[i] * av[i];
        g_wall[idx] = s;
    }
    if (idx < 24) {
        int r = idx >> 3, rem = idx & 7, head = rem >> 1, pq = rem & 1;
        const float* bb = wb + r * HH + head * HF;
        const float* av = aW + r * 2 * HF + pq * HF;
        float s = 0.f;
        for (int i = 0; i < HF; i++) s += bb[i] * av[i];
        g_wallc[idx] = s;
    }
}

// ---------------- per-node projections: smem-tiled -------------------------
__global__ void __launch_bounds__(128) node_kernel(const float* __restrict__ h) {
    __shared__ float sh[64][132];
    __shared__ float sw[28][132];
    __shared__ float sc[28];
    int t = threadIdx.x;
    int nb = blockIdx.x * 64;

    #pragma unroll
    for (int i = 0; i < 16; i++) {
        int lin = i * 128 + t;
        int row = lin >> 5, kq = (lin & 31) << 2;
        int gn = nb + row;
        float4 v = make_float4(0.f, 0.f, 0.f, 0.f);
        if (gn < NN) v = *(const float4*)(h + (size_t)gn * IN_F + kq);
        *(float4*)&sh[row][kq] = v;
    }
    #pragma unroll
    for (int i = 0; i < 7; i++) {
        int lin = i * 128 + t;
        if (lin < 28 * 32) {
            int row = lin >> 5, kq = (lin & 31) << 2;
            *(float4*)&sw[row][kq] = *(const float4*)(g_wall + row * IN_F + kq);
        }
    }
    if (t < 28) sc[t] = g_wallc[t];
    __syncthreads();

    int nrow = t >> 2, sub = t & 3;
    float acc0[7], acc1[7];
    #pragma unroll
    for (int j = 0; j < 7; j++) { acc0[j] = 0.f; acc1[j] = 0.f; }
    for (int k = 0; k < IN_F; k++) {
        float h0 = sh[nrow][k];
        float h1 = sh[nrow + 32][k];
        #pragma unroll
        for (int j = 0; j < 7; j++) {
            float w = sw[sub * 7 + j][k];
            acc0[j] = fmaf(h0, w, acc0[j]);
            acc1[j] = fmaf(h1, w, acc1[j]);
        }
    }
    #pragma unroll
    for (int m = 0; m < 2; m++) {
        int gn = nb + nrow + 32 * m;
        if (gn >= NN) continue;
        #pragma unroll
        for (int j = 0; j < 7; j++) {
            int v = sub * 7 + j;
            if (v >= 26) continue;
            float val = (m ? acc1[j] : acc0[j]) + sc[v];
            if (v < 24) {
                int r = v >> 3, rem = v & 7, head = rem >> 1, pq = rem & 1;
                int off = (gn * RR + r) * AHD + head;
                if (pq == 0) g_p[off] = val; else g_q[off] = val;
            } else if (v == 24) g_as[gn] = val;
            else                g_ad[gn] = val;
        }
    }
}

// ---------------- CSR build ------------------------------------------------
__global__ void count_kernel(const int* __restrict__ dst) {
    int idx = blockIdx.x * blockDim.x + threadIdx.x;
    if (idx >= RR * EE) return;
    int r = idx / EE;
    atomicAdd(&g_cnt[r * NN + dst[idx]], 1);
}

__global__ void __launch_bounds__(1024) scan_kernel() {
    __shared__ int ssum[1024];
    int t = threadIdx.x;
    const int PER = (NR + 1023) / 1024;
    int base = t * PER;
    int s = 0;
    for (int i = 0; i < PER; i++) {
        int idx = base + i;
        if (idx < NR) s += g_cnt[idx];
    }
    ssum[t] = s;
    __syncthreads();
    for (int o = 1; o < 1024; o <<= 1) {
        int w = 0;
        if (t >= o) w = ssum[t - o];
        __syncthreads();
        ssum[t] += w;
        __syncthreads();
    }
    int run = ssum[t] - s;
    for (int i = 0; i < PER; i++) {
        int idx = base + i;
        if (idx < NR) { g_off[idx] = run; run += g_cnt[idx]; }
    }
    if (t == 1023) g_off[NR] = run;
}

__global__ void scatter_kernel(const int* __restrict__ dst) {
    int idx = blockIdx.x * blockDim.x + threadIdx.x;
    if (idx >= RR * EE) return;
    int r = idx / EE;
    int seg = r * NN + dst[idx];
    int p = atomicAdd(&g_pos[seg], 1);
    g_elist[g_off[seg] + p] = idx;
}

// ---------------- edge phase: sign, alpha, exp (no atomics) ----------------
__global__ void edge_kernel(const int* __restrict__ src, const int* __restrict__ dst,
                            const float* __restrict__ ab) {
    int idx = blockIdx.x * blockDim.x + threadIdx.x;
    if (idx >= RR * EE) return;
    int r = idx / EE;
    int s = src[idx], d = dst[idx];
    float sc = g_as[s] + g_ad[d];
    float sg = (sc > 0.f) ? 1.f : ((sc < 0.f) ? -1.f : 0.f);
    float4 pv = *(const float4*)(g_p + (s*RR + r)*AHD);
    float4 qv = *(const float4*)(g_q + (d*RR + r)*AHD);
    float abr = ab[r];
    float4 ex;
    ex.x = expf(lrelu(sg*pv.x + qv.x + abr));
    ex.y = expf(lrelu(sg*pv.y + qv.y + abr));
    ex.z = expf(lrelu(sg*pv.z + qv.z + abr));
    ex.w = expf(lrelu(sg*pv.w + qv.w + abr));
    *(float4*)(g_ex + (size_t)idx * AHD) = ex;
    g_sgn[idx] = sg;
}

// ---------------- CSR aggregate: warp per (r,dst), fp16 gather -------------
__global__ void __launch_bounds__(256) aggregate_csr_kernel(const int* __restrict__ src) {
    __shared__ float4 scf[8][32];
    __shared__ int    ssrc[8][32];
    int gw   = (blockIdx.x * blockDim.x + threadIdx.x) >> 5;
    int lane = threadIdx.x & 31;
    int wslot = threadIdx.x >> 5;
    if (gw >= NR) return;
    int r = gw / NN;
    int beg = g_off[gw], end = g_off[gw + 1];
    float* orow = g_oacc + (size_t)gw * HH + lane * 8;

    if (beg == end) {
        float4 z = make_float4(0.f, 0.f, 0.f, 0.f);
        *(float4*)orow = z;
        *(float4*)(orow + 4) = z;
        return;
    }

    // denominator over incident edges (4 heads)
    float dx = 0.f, dy = 0.f, dz = 0.f, dw = 0.f;
    for (int j = beg + lane; j < end; j += 32) {
        int idx = g_elist[j];
        float4 e = *(const float4*)(g_ex + (size_t)idx * AHD);
        dx += e.x; dy += e.y; dz += e.z; dw += e.w;
    }
    #pragma unroll
    for (int o = 16; o; o >>= 1) {
        dx += __shfl_xor_sync(0xffffffffu, dx, o);
        dy += __shfl_xor_sync(0xffffffffu, dy, o);
        dz += __shfl_xor_sync(0xffffffffu, dz, o);
        dw += __shfl_xor_sync(0xffffffffu, dw, o);
    }
    float rdx = 1.f / dx, rdy = 1.f / dy, rdz = 1.f / dz, rdw = 1.f / dw;
    int head = lane >> 3;

    const __half* hwbase = g_hwh + (size_t)r * NN * HH;
    float a0=0.f,a1=0.f,a2=0.f,a3=0.f,a4=0.f,a5=0.f,a6=0.f,a7=0.f;

    for (int base = beg; base < end; base += 32) {
        int j = base + lane;
        int cnt = min(32, end - base);
        if (j < end) {
            int idx = g_elist[j];
            float4 e = *(const float4*)(g_ex + (size_t)idx * AHD);
            float sg = g_sgn[idx];
            scf[wslot][lane] = make_float4(sg*e.x*rdx, sg*e.y*rdy, sg*e.z*rdz, sg*e.w*rdw);
            ssrc[wslot][lane] = src[idx];
        }
        __syncwarp();
        #pragma unroll 4
        for (int k = 0; k < cnt; k++) {
            int s = ssrc[wslot][k];
            float4 c4 = scf[wslot][k];
            float cf = (head == 0) ? c4.x : (head == 1) ? c4.y : (head == 2) ? c4.z : c4.w;
            uint4 hv = *(const uint4*)(hwbase + (size_t)s * HH + lane * 8);
            float2 f0 = __half22float2(*(__half2*)&hv.x);
            float2 f1 = __half22float2(*(__half2*)&hv.y);
            float2 f2 = __half22float2(*(__half2*)&hv.z);
            float2 f3 = __half22float2(*(__half2*)&hv.w);
            a0 = fmaf(cf, f0.x, a0); a1 = fmaf(cf, f0.y, a1);
            a2 = fmaf(cf, f1.x, a2); a3 = fmaf(cf, f1.y, a3);
            a4 = fmaf(cf, f2.x, a4); a5 = fmaf(cf, f2.y, a5);
            a6 = fmaf(cf, f3.x, a6); a7 = fmaf(cf, f3.y, a7);
        }
        __syncwarp();
    }
    *(float4*)orow       = make_float4(a0, a1, a2, a3);
    *(float4*)(orow + 4) = make_float4(a4, a5, a6, a7);
}

// ---------------- launch ---------------------------------------------------
extern "C" void kernel_launch(void* const* d_in, const int* in_sizes, int n_in,
                              void* d_out, int out_size) {
    const float* h    = (const float*)d_in[0];
    const float* dW   = (const float*)d_in[1];
    const float* db   = (const float*)d_in[2];
    const float* fW   = (const float*)d_in[3];
    const float* fb   = (const float*)d_in[4];
    const float* wW   = (const float*)d_in[5];
    const float* wb   = (const float*)d_in[6];
    const float* aW   = (const float*)d_in[7];
    const float* ab   = (const float*)d_in[8];
    const float* linW = (const float*)d_in[9];
    const float* linb = (const float*)d_in[10];
    const int*   src  = (const int*)d_in[11];
    const int*   dst  = (const int*)d_in[12];
    float* out = (float*)d_out;

    float *oacc, *wWt, *linWt;
    __half* hwh;
    int *cnt, *pos;
    cudaGetSymbolAddress((void**)&hwh,   g_hwh);
    cudaGetSymbolAddress((void**)&oacc,  g_oacc);
    cudaGetSymbolAddress((void**)&wWt,   g_wWt);
    cudaGetSymbolAddress((void**)&linWt, g_linWt);
    cudaGetSymbolAddress((void**)&cnt,   g_cnt);
    cudaGetSymbolAddress((void**)&pos,   g_pos);

    int mtiles = (NN + 127) / 128;

    // Launch order arranged so GEMM1 is the 6th launch (ncu captures -s 5 -c 1).
    transpose_weights_kernel<<<(HH * RH + 255) / 256, 256>>>(wW, linW);   // 1
    prep_kernel<<<1, 128>>>(dW, db, fW, fb);                              // 2
    prep_pq_kernel<<<(24 * IN_F + 255) / 256, 256>>>(wW, wb, aW);         // 3
    node_kernel<<<(NN + 63) / 64, 128>>>(h);                              // 4
    cudaMemsetAsync(cnt, 0, NR * sizeof(int), 0);                         // 5

    // 6 (captured): hw[r] = h @ wW[r] + wb[r] (all relations, fp16 output)
    mma_gemm_kernel<<<dim3(2, mtiles, RR), 256>>>(
        h, IN_F, 30, 0,
        wWt, IN_F, (size_t)HH * IN_F,
        wb, HH,
        nullptr, hwh, HH, (size_t)NN * HH,
        NN, IN_F);

    cudaMemsetAsync(pos, 0, NR * sizeof(int), 0);                         // 7
    count_kernel<<<(RR * EE + 255) / 256, 256>>>(dst);                    // 8
    scan_kernel<<<1, 1024>>>();                                           // 9
    scatter_kernel<<<(RR * EE + 255) / 256, 256>>>(dst);                  // 10
    edge_kernel<<<(RR * EE + 255) / 256, 256>>>(src, dst, ab);            // 11
    aggregate_csr_kernel<<<(NR + 7) / 8, 256>>>(src);                     // 12

    // out = concat_r(oacc_r) @ linW + linb  (A segmented by relation slab)
    mma_gemm_kernel<<<dim3(2, mtiles, 1), 256>>>(
        oacc, HH, 8, (size_t)NN * HH,
        linWt, RH, 0,
        linb, 0,
        out, nullptr, HH, 0,
        NN, RH);
}